// round 1
// baseline (speedup 1.0000x reference)
#include <cuda_runtime.h>
#include <cuda_bf16.h>
#include <cstdint>
#include <math.h>

#define B_ 8
#define T_ 4096
#define D_ 1024
#define H_ 64
#define BT_ (B_*T_)   // 32768

// ---------------- scratch (device globals; allocation-free contract) ----------------
__device__ __nv_bfloat16 g_xn [(size_t)BT_*D_];      // normalized x, bf16
__device__ __nv_bfloat16 g_xbz[(size_t)BT_*2048];    // [x_b | z], bf16
__device__ __nv_bfloat16 g_xc [(size_t)BT_*D_];      // conv+silu output, bf16
__device__ float         g_proj[(size_t)BT_*1152];   // xc @ [dw;Bw;Dw]^T, fp32
__device__ float         g_a  [(size_t)512*4096];    // delta*A_log, [bh][t]
__device__ float         g_bu [(size_t)512*4096];    // delta*(p2+Bb), [bh][t]
__device__ __nv_bfloat16 g_h  [(size_t)BT_*H_];      // scan state, token-major
__device__ __nv_bfloat16 g_u  [(size_t)BT_*D_];      // gated pre-output, bf16
__device__ __nv_bfloat16 g_Wa [(size_t)2048*1024];   // [W1;W2]
__device__ __nv_bfloat16 g_Wb [(size_t)1152*1024];   // [dw;Bw;Dw]
__device__ __nv_bfloat16 g_Wc [(size_t)1024*64];     // Cw
__device__ __nv_bfloat16 g_Wd [(size_t)1024*1024];   // Wlast

// ---------------- helpers ----------------
__device__ __forceinline__ float siluf(float v){ return v / (1.f + expf(-v)); }
__device__ __forceinline__ float softplusf(float v){ return (v > 20.f) ? v : log1pf(expf(v)); }
__device__ __forceinline__ float clipf(float v){ return fminf(fmaxf(v, -20.f), 20.f); }

__device__ __forceinline__ void ldsm_x4(uint32_t addr, uint32_t &r0, uint32_t &r1, uint32_t &r2, uint32_t &r3){
    asm volatile("ldmatrix.sync.aligned.m8n8.x4.shared.b16 {%0,%1,%2,%3}, [%4];\n"
        : "=r"(r0), "=r"(r1), "=r"(r2), "=r"(r3) : "r"(addr));
}
__device__ __forceinline__ void mma16816(float* c, uint32_t a0, uint32_t a1, uint32_t a2, uint32_t a3,
                                         uint32_t b0, uint32_t b1){
    asm volatile("mma.sync.aligned.m16n8k16.row.col.f32.bf16.bf16.f32 "
                 "{%0,%1,%2,%3},{%4,%5,%6,%7},{%8,%9},{%0,%1,%2,%3};\n"
        : "+f"(c[0]), "+f"(c[1]), "+f"(c[2]), "+f"(c[3])
        : "r"(a0), "r"(a1), "r"(a2), "r"(a3), "r"(b0), "r"(b1));
}

// ---------------- weight conversion / packing ----------------
__global__ void convert_weights(const float* __restrict__ W1, const float* __restrict__ W2,
                                const float* __restrict__ dwp, const float* __restrict__ Bwp,
                                const float* __restrict__ Dwp, const float* __restrict__ Cwp,
                                const float* __restrict__ Wlastp){
    int i = blockIdx.x * blockDim.x + threadIdx.x;
    const int NWa = 2048*1024, NWb = 1152*1024, NWc = 1024*64, NWd = 1024*1024;
    if (i < NWa){
        g_Wa[i] = __float2bfloat16(i < 1048576 ? W1[i] : W2[i - 1048576]);
    } else if (i < NWa + NWb){
        int j = i - NWa;
        float v = (j < 65536) ? dwp[j] : (j < 131072) ? Bwp[j - 65536] : Dwp[j - 131072];
        g_Wb[j] = __float2bfloat16(v);
    } else if (i < NWa + NWb + NWc){
        int j = i - NWa - NWb;
        g_Wc[j] = __float2bfloat16(Cwp[j]);
    } else if (i < NWa + NWb + NWc + NWd){
        int j = i - NWa - NWb - NWc;
        g_Wd[j] = __float2bfloat16(Wlastp[j]);
    }
}

// ---------------- RMSNorm ----------------
__global__ void rmsnorm_kernel(const float* __restrict__ x, const float* __restrict__ w){
    __shared__ float ws[8];
    int m = blockIdx.x, tid = threadIdx.x;
    float4 v = ((const float4*)(x + (size_t)m * D_))[tid];
    float ss = v.x*v.x + v.y*v.y + v.z*v.z + v.w*v.w;
    #pragma unroll
    for (int d = 16; d; d >>= 1) ss += __shfl_xor_sync(0xffffffffu, ss, d);
    if ((tid & 31) == 0) ws[tid >> 5] = ss;
    __syncthreads();
    if (tid == 0){ float s = 0.f; for (int i = 0; i < 8; i++) s += ws[i]; ws[0] = s; }
    __syncthreads();
    float scale = rsqrtf(ws[0] * (1.f / D_) + 1.1920928955078125e-07f);
    float4 wv = ((const float4*)w)[tid];
    __nv_bfloat162 p0 = __floats2bfloat162_rn(v.x*scale*wv.x, v.y*scale*wv.y);
    __nv_bfloat162 p1 = __floats2bfloat162_rn(v.z*scale*wv.z, v.w*scale*wv.w);
    __nv_bfloat162* dst = (__nv_bfloat162*)(g_xn + (size_t)m * D_) + tid * 2;
    dst[0] = p0; dst[1] = p1;
}

// ---------------- causal depthwise conv (k=3) + SiLU ----------------
__global__ void conv_silu_kernel(const float* __restrict__ conv_w, const float* __restrict__ conv_b){
    int idx = blockIdx.x * blockDim.x + threadIdx.x;   // BT_*512 threads, 2 channels each
    int d2 = idx & 511; int bt = idx >> 9;
    int t = bt & (T_ - 1);
    int d = d2 * 2;
    const __nv_bfloat162* row2 = (const __nv_bfloat162*)(g_xbz + (size_t)bt * 2048 + d);
    __nv_bfloat162 zero2; zero2.x = __float2bfloat16(0.f); zero2.y = __float2bfloat16(0.f);
    __nv_bfloat162 c2 = *row2;
    __nv_bfloat162 c1 = (t >= 1) ? *(const __nv_bfloat162*)(g_xbz + (size_t)(bt-1) * 2048 + d) : zero2;
    __nv_bfloat162 c0 = (t >= 2) ? *(const __nv_bfloat162*)(g_xbz + (size_t)(bt-2) * 2048 + d) : zero2;
    float w00 = conv_w[d*3+0], w01 = conv_w[d*3+1], w02 = conv_w[d*3+2];
    float w10 = conv_w[d*3+3], w11 = conv_w[d*3+4], w12 = conv_w[d*3+5];
    float r0 = __bfloat162float(c0.x)*w00 + __bfloat162float(c1.x)*w01 + __bfloat162float(c2.x)*w02 + conv_b[d];
    float r1 = __bfloat162float(c0.y)*w10 + __bfloat162float(c1.y)*w11 + __bfloat162float(c2.y)*w12 + conv_b[d+1];
    r0 = siluf(r0); r1 = siluf(r1);
    *(__nv_bfloat162*)(g_xc + (size_t)bt * 1024 + d) = __floats2bfloat162_rn(r0, r1);
}

// ---------------- scan prep: proj cols [0,128) -> a, bu in [bh][t] layout ----------------
__global__ void prep_scan_kernel(const float* __restrict__ Aparam, const float* __restrict__ Bb,
                                 const float* __restrict__ db){
    __shared__ float sm[64][129];
    int row0 = blockIdx.x * 64;     // global token base
    int tid = threadIdx.x;          // 256
    for (int idx = tid; idx < 64*128; idx += 256){
        int r = idx >> 7, c = idx & 127;
        sm[r][c] = g_proj[(size_t)(row0 + r) * 1152 + c];
    }
    __syncthreads();
    int b = row0 >> 12;             // /4096
    int t0 = row0 & (T_ - 1);
    for (int idx = tid; idx < 64*64; idx += 256){
        int h = idx >> 6, tt = idx & 63;
        float p1 = sm[tt][h], p2 = sm[tt][64 + h];
        float delta = softplusf(p1 + db[h]);
        float alog = -softplusf(Aparam[h]);
        size_t o = (size_t)(b * 64 + h) * 4096 + t0 + tt;
        g_a[o]  = delta * alog;
        g_bu[o] = delta * (p2 + Bb[h]);
    }
}

// ---------------- block-parallel scan over T per (b,h) ----------------
__device__ __forceinline__ float block_excl_prefix(float total, float* wsum, int tid){
    __syncthreads();                    // protect wsum reuse across calls
    int lane = tid & 31, wid = tid >> 5;   // 16 warps
    float v = total;
    #pragma unroll
    for (int d = 1; d < 32; d <<= 1){
        float o = __shfl_up_sync(0xffffffffu, v, d);
        if (lane >= d) v += o;
    }
    if (lane == 31) wsum[wid] = v;
    __syncthreads();
    if (tid == 0){
        float s = 0.f;
        for (int i = 0; i < 16; i++){ float t = wsum[i]; wsum[i] = s; s += t; }  // exclusive
    }
    __syncthreads();
    return wsum[wid] + v - total;       // exclusive prefix for this thread
}

__global__ void scan_kernel(){
    __shared__ float wsum[16];
    int bh = blockIdx.x;
    int b = bh >> 6, hh = bh & 63;
    int tid = threadIdx.x;              // 512 threads, 8 elems each
    size_t base = (size_t)bh * 4096 + tid * 8;
    float av[8], bv[8], ev[8], cv[8];
    {
        float4 a0 = *(const float4*)(g_a + base);
        float4 a1 = *(const float4*)(g_a + base + 4);
        av[0]=a0.x; av[1]=a0.y; av[2]=a0.z; av[3]=a0.w;
        av[4]=a1.x; av[5]=a1.y; av[6]=a1.z; av[7]=a1.w;
        float4 b0 = *(const float4*)(g_bu + base);
        float4 b1 = *(const float4*)(g_bu + base + 4);
        bv[0]=b0.x; bv[1]=b0.y; bv[2]=b0.z; bv[3]=b0.w;
        bv[4]=b1.x; bv[5]=b1.y; bv[6]=b1.z; bv[7]=b1.w;
    }
    // inclusive local scan of a
    float s = 0.f;
    #pragma unroll
    for (int i = 0; i < 8; i++){ s += av[i]; av[i] = s; }
    float pa = block_excl_prefix(av[7], wsum, tid);
    // A_cum / A_shift / c terms
    #pragma unroll
    for (int i = 0; i < 8; i++){
        float S = pa + av[i];
        float Sprev = pa + (i ? av[i-1] : 0.f);
        float Ac  = clipf(S);
        float Ash = clipf(Sprev);
        ev[i] = expf(Ac);
        cv[i] = bv[i] * expf(-Ash);
    }
    // inclusive local scan of c
    s = 0.f;
    #pragma unroll
    for (int i = 0; i < 8; i++){ s += cv[i]; cv[i] = s; }
    float pb = block_excl_prefix(cv[7], wsum, tid);
    // h = exp(A_cum) * cumsum  -> token-major bf16
    int t = tid * 8;
    #pragma unroll
    for (int i = 0; i < 8; i++){
        float hval = ev[i] * (pb + cv[i]);
        g_h[(size_t)(b * T_ + t + i) * 64 + hh] = __float2bfloat16(hval);
    }
}

// ---------------- generic bf16 GEMM: C[M,N] = A[M,K] @ W[N,K]^T, fused epilogues ----------------
// EPI 0: store bf16 to g_xbz (ld 2048)
// EPI 1: store f32  to g_proj (ld 1152)
// EPI 2: u = (acc + Cb + Db + projDw) * silu(z) -> g_u bf16
// EPI 3: out = acc + x (fp32)
template<int EPI, int KDIM>
__global__ void __launch_bounds__(256, 2) gemm_bf16(
    const float* __restrict__ aux0, const float* __restrict__ aux1,
    const float* __restrict__ xres, float* __restrict__ outp)
{
    const __nv_bfloat16* __restrict__ Ag = (EPI==0) ? g_xn : (EPI==1) ? g_xc : (EPI==2) ? g_h : g_u;
    const __nv_bfloat16* __restrict__ Wg = (EPI==0) ? g_Wa : (EPI==1) ? g_Wb : (EPI==2) ? g_Wc : g_Wd;
    extern __shared__ char smem_raw[];
    const int tid = threadIdx.x;
    const int lane = tid & 31, warp = tid >> 5;
    const int wm = warp >> 1, wn = warp & 1;
    const size_t m0 = (size_t)blockIdx.y * 128;
    const int n0 = blockIdx.x * 128;
    constexpr int KT = KDIM / 64;
    const uint32_t sbase = (uint32_t)__cvta_generic_to_shared(smem_raw);

    float acc[2][8][4];
    #pragma unroll
    for (int i = 0; i < 2; i++)
        #pragma unroll
        for (int j = 0; j < 8; j++)
            #pragma unroll
            for (int k = 0; k < 4; k++) acc[i][j][k] = 0.f;

    auto load_stage = [&](int kt, int st){
        const __nv_bfloat16* Asrc = Ag + m0 * KDIM + kt * 64;
        const __nv_bfloat16* Wsrc = Wg + (size_t)n0 * KDIM + kt * 64;
        uint32_t abase = sbase + st * 32768;
        uint32_t wbase = abase + 16384;
        #pragma unroll
        for (int i = 0; i < 4; i++){
            int cc = i * 256 + tid;
            int r = cc >> 3, c = cc & 7;
            int sw = ((c ^ (r & 7)) << 4);
            uint32_t da = abase + r * 128 + sw;
            const void* pa = Asrc + (size_t)r * KDIM + c * 8;
            asm volatile("cp.async.cg.shared.global [%0], [%1], 16;\n" :: "r"(da), "l"(pa));
            uint32_t dw_ = wbase + r * 128 + sw;
            const void* pw = Wsrc + (size_t)r * KDIM + c * 8;
            asm volatile("cp.async.cg.shared.global [%0], [%1], 16;\n" :: "r"(dw_), "l"(pw));
        }
    };

    load_stage(0, 0);
    asm volatile("cp.async.commit_group;\n" ::: "memory");

    for (int kt = 0; kt < KT; kt++){
        if (kt + 1 < KT){
            load_stage(kt + 1, (kt + 1) & 1);
            asm volatile("cp.async.commit_group;\n" ::: "memory");
            asm volatile("cp.async.wait_group 1;\n" ::: "memory");
        } else {
            asm volatile("cp.async.wait_group 0;\n" ::: "memory");
        }
        __syncthreads();
        const int st = kt & 1;
        const uint32_t abase = sbase + st * 32768;
        const uint32_t wbase = abase + 16384;
        #pragma unroll
        for (int ks = 0; ks < 4; ks++){
            uint32_t af[2][4];
            #pragma unroll
            for (int mi = 0; mi < 2; mi++){
                int row = wm * 32 + mi * 16 + (lane & 15);
                int chunk = ks * 2 + (lane >> 4);
                uint32_t addr = abase + row * 128 + ((chunk ^ (row & 7)) << 4);
                ldsm_x4(addr, af[mi][0], af[mi][1], af[mi][2], af[mi][3]);
            }
            #pragma unroll
            for (int nq = 0; nq < 4; nq++){
                int g = lane >> 3, rr = lane & 7;
                int row = wn * 64 + nq * 16 + (g >> 1) * 8 + rr;
                int chunk = ks * 2 + (g & 1);
                uint32_t addr = wbase + row * 128 + ((chunk ^ (row & 7)) << 4);
                uint32_t b0, b1, b2, b3;
                ldsm_x4(addr, b0, b1, b2, b3);
                mma16816(acc[0][nq*2],   af[0][0], af[0][1], af[0][2], af[0][3], b0, b1);
                mma16816(acc[0][nq*2+1], af[0][0], af[0][1], af[0][2], af[0][3], b2, b3);
                mma16816(acc[1][nq*2],   af[1][0], af[1][1], af[1][2], af[1][3], b0, b1);
                mma16816(acc[1][nq*2+1], af[1][0], af[1][1], af[1][2], af[1][3], b2, b3);
            }
        }
        __syncthreads();
    }

    // epilogue
    #pragma unroll
    for (int mi = 0; mi < 2; mi++){
        #pragma unroll
        for (int nj = 0; nj < 8; nj++){
            int mbase = (int)m0 + wm * 32 + mi * 16 + (lane >> 2);
            int nb = n0 + wn * 64 + nj * 8 + (lane & 3) * 2;
            #pragma unroll
            for (int hh = 0; hh < 2; hh++){
                int m = mbase + hh * 8;
                float v0 = acc[mi][nj][hh*2], v1 = acc[mi][nj][hh*2+1];
                if (EPI == 0){
                    *(__nv_bfloat162*)(g_xbz + (size_t)m * 2048 + nb) = __floats2bfloat162_rn(v0, v1);
                } else if (EPI == 1){
                    *(float2*)(g_proj + (size_t)m * 1152 + nb) = make_float2(v0, v1);
                } else if (EPI == 2){
                    __nv_bfloat162 zz = *(const __nv_bfloat162*)(g_xbz + (size_t)m * 2048 + 1024 + nb);
                    float z0 = __bfloat162float(zz.x), z1 = __bfloat162float(zz.y);
                    float d0 = g_proj[(size_t)m * 1152 + 128 + nb];
                    float d1 = g_proj[(size_t)m * 1152 + 128 + nb + 1];
                    float u0 = (v0 + aux0[nb]   + aux1[nb]   + d0) * siluf(z0);
                    float u1 = (v1 + aux0[nb+1] + aux1[nb+1] + d1) * siluf(z1);
                    *(__nv_bfloat162*)(g_u + (size_t)m * 1024 + nb) = __floats2bfloat162_rn(u0, u1);
                } else {
                    float2 xr = *(const float2*)(xres + (size_t)m * 1024 + nb);
                    *(float2*)(outp + (size_t)m * 1024 + nb) = make_float2(v0 + xr.x, v1 + xr.y);
                }
            }
        }
    }
}

// ---------------- launch ----------------
extern "C" void kernel_launch(void* const* d_in, const int* in_sizes, int n_in,
                              void* d_out, int out_size){
    const float* x      = (const float*)d_in[0];
    const float* norm_w = (const float*)d_in[1];
    const float* W1     = (const float*)d_in[2];
    const float* W2     = (const float*)d_in[3];
    const float* Wlast  = (const float*)d_in[4];
    const float* conv_w = (const float*)d_in[5];
    const float* conv_b = (const float*)d_in[6];
    const float* Ap     = (const float*)d_in[7];
    const float* Bw     = (const float*)d_in[8];
    const float* Bb     = (const float*)d_in[9];
    const float* Cw     = (const float*)d_in[10];
    const float* Cb     = (const float*)d_in[11];
    const float* Dw     = (const float*)d_in[12];
    const float* Db     = (const float*)d_in[13];
    const float* dwp    = (const float*)d_in[14];
    const float* dbp    = (const float*)d_in[15];
    float* out = (float*)d_out;

    cudaFuncSetAttribute((const void*)gemm_bf16<0,1024>, cudaFuncAttributeMaxDynamicSharedMemorySize, 65536);
    cudaFuncSetAttribute((const void*)gemm_bf16<1,1024>, cudaFuncAttributeMaxDynamicSharedMemorySize, 65536);
    cudaFuncSetAttribute((const void*)gemm_bf16<2,64>,   cudaFuncAttributeMaxDynamicSharedMemorySize, 65536);
    cudaFuncSetAttribute((const void*)gemm_bf16<3,1024>, cudaFuncAttributeMaxDynamicSharedMemorySize, 65536);

    convert_weights<<<17152, 256>>>(W1, W2, dwp, Bw, Dw, Cw, Wlast);
    rmsnorm_kernel<<<32768, 256>>>(x, norm_w);
    gemm_bf16<0,1024><<<dim3(16, 256), 256, 65536>>>(nullptr, nullptr, nullptr, nullptr);
    conv_silu_kernel<<<65536, 256>>>(conv_w, conv_b);
    gemm_bf16<1,1024><<<dim3(9, 256), 256, 65536>>>(nullptr, nullptr, nullptr, nullptr);
    prep_scan_kernel<<<512, 256>>>(Ap, Bb, dbp);
    scan_kernel<<<512, 512>>>();
    gemm_bf16<2,64><<<dim3(8, 256), 256, 65536>>>(Cb, Db, nullptr, nullptr);
    gemm_bf16<3,1024><<<dim3(8, 256), 256, 65536>>>(nullptr, nullptr, x, out);
}